// round 1
// baseline (speedup 1.0000x reference)
#include <cuda_runtime.h>
#include <math.h>

#define HID 128
#define NEAR_T 0.01f
#define FAR_T 10.0f
#define MAX_IT 32

// ---- packed f32x2 helpers (Blackwell) ----
#define FMA2(acc, a, b) \
    asm("fma.rn.f32x2 %0, %1, %2, %0;" : "+l"(acc) : "l"(a), "l"(b))
#define PACK2(dst, lo, hi) \
    asm("mov.b64 %0, {%1, %2};" : "=l"(dst) : "f"(lo), "f"(hi))
#define UNPACK2(lo, hi, src) \
    asm("mov.b64 {%0, %1}, %2;" : "=f"(lo), "=f"(hi) : "l"(src))

// SMEM layout (floats):
//  sW1   [3*128]   = 384      (row-major [3][128])
//  sB1   [128]
//  sW2T  [128*128] = 16384    (transposed: sW2T[j*128+k] = W2[k][j])
//  sB2   [128]
//  sW3   [128]
//  sWc1  [3*128]   = 384
//  sBc1  [128]
//  sWc2  [128*3]   = 384
//  sBc2  [4]
// total = 18052 floats = 72208 bytes
#define SMEM_FLOATS 18052

extern __shared__ float smem[];

__global__ void __launch_bounds__(128, 2)
sphere_trace_kernel(const float* __restrict__ org,
                    const float* __restrict__ dir,
                    const float* __restrict__ W1, const float* __restrict__ b1,
                    const float* __restrict__ W2, const float* __restrict__ b2,
                    const float* __restrict__ W3, const float* __restrict__ b3,
                    const float* __restrict__ Wc1, const float* __restrict__ bc1,
                    const float* __restrict__ Wc2, const float* __restrict__ bc2,
                    float* __restrict__ out, int N)
{
    float* sW1  = smem;            // 384
    float* sB1  = sW1  + 384;      // 128
    float* sW2T = sB1  + 128;      // 16384 (offset 512 floats = 2048B, 16B aligned)
    float* sB2  = sW2T + 16384;    // 128
    float* sW3  = sB2  + 128;      // 128
    float* sWc1 = sW3  + 128;      // 384
    float* sBc1 = sWc1 + 384;      // 128
    float* sWc2 = sBc1 + 128;      // 384
    float* sBc2 = sWc2 + 384;      // 4

    const int tid = threadIdx.x;

    // ---- cooperative SMEM load ----
    #pragma unroll
    for (int i = tid; i < 384; i += 128) { sW1[i] = W1[i]; sWc1[i] = Wc1[i]; sWc2[i] = Wc2[i]; }
    {
        int i = tid;
        sB1[i] = b1[i]; sB2[i] = b2[i]; sW3[i] = W3[i]; sBc1[i] = bc1[i];
    }
    // transpose W2 [k][j] -> sW2T [j][k]
    for (int i = tid; i < 16384; i += 128) {
        int j = i >> 7, k = i & 127;
        sW2T[i] = W2[k * HID + j];
    }
    if (tid < 3) sBc2[tid] = bc2[tid];
    if (tid == 3) sBc2[3] = 0.0f;
    const float bias3 = b3[0];
    __syncthreads();

    int ray = blockIdx.x * 128 + tid;
    const bool active = (ray < N);
    const int r = active ? ray : (N - 1);

    float px = org[3*r],  py = org[3*r+1],  pz = org[3*r+2];
    const float dx = dir[3*r], dy = dir[3*r+1], dz = dir[3*r+2];

    float dist = 0.0f;
    bool hit = false;
    bool frozen = false;

    unsigned long long hp[HID / 2];   // h1 packed as f32x2 pairs along k

    for (int it = 0; it < MAX_IT; ++it) {
        if (!frozen) {
            // ---- layer 1: h1 = relu(p @ W1 + b1) ----
            #pragma unroll
            for (int m = 0; m < HID / 2; ++m) {
                const int j0 = 2 * m, j1 = 2 * m + 1;
                float v0 = fmaf(px, sW1[j0],
                           fmaf(py, sW1[HID + j0],
                           fmaf(pz, sW1[2*HID + j0], sB1[j0])));
                float v1 = fmaf(px, sW1[j1],
                           fmaf(py, sW1[HID + j1],
                           fmaf(pz, sW1[2*HID + j1], sB1[j1])));
                v0 = fmaxf(v0, 0.0f);
                v1 = fmaxf(v1, 0.0f);
                PACK2(hp[m], v0, v1);
            }

            // ---- layer 2 + layer 3 fused: sdf = relu(h1@W2+b2) @ W3 + b3 ----
            float sdf = bias3;
            const ulonglong2* wrow = reinterpret_cast<const ulonglong2*>(sW2T);
            for (int j = 0; j < HID; ++j) {
                unsigned long long acca, accb = 0ull;
                PACK2(acca, sB2[j], 0.0f);
                const ulonglong2* wj = wrow + j * (HID / 4);
                #pragma unroll
                for (int m = 0; m < HID / 4; ++m) {
                    ulonglong2 w = wj[m];            // LDS.128 broadcast (uniform addr)
                    FMA2(acca, hp[2*m],     w.x);
                    FMA2(accb, hp[2*m + 1], w.y);
                }
                float a0, a1, c0, c1;
                UNPACK2(a0, a1, acca);
                UNPACK2(c0, c1, accb);
                float h2 = (a0 + a1) + (c0 + c1);
                h2 = fmaxf(h2, 0.0f);
                sdf = fmaf(h2, sW3[j], sdf);
            }

            // ---- march update ----
            const bool valid = (sdf <= NEAR_T) && (dist < FAR_T);
            hit = hit || valid;
            if (valid) {
                frozen = true;   // state frozen => valid holds forever
            } else {
                dist += sdf;
                px = fmaf(dx, sdf, px);
                py = fmaf(dy, sdf, py);
                pz = fmaf(dz, sdf, pz);
            }
        }
        if (__all_sync(0xffffffffu, frozen)) break;
    }

    const bool mask = hit || (dist < FAR_T);

    // ---- color MLP: sigmoid(relu(p@Wc1+bc1) @ Wc2 + bc2) ----
    float c0 = sBc2[0], c1 = sBc2[1], c2 = sBc2[2];
    for (int j = 0; j < HID; ++j) {
        float h = fmaf(px, sWc1[j],
                  fmaf(py, sWc1[HID + j],
                  fmaf(pz, sWc1[2*HID + j], sBc1[j])));
        h = fmaxf(h, 0.0f);
        c0 = fmaf(h, sWc2[3*j],     c0);
        c1 = fmaf(h, sWc2[3*j + 1], c1);
        c2 = fmaf(h, sWc2[3*j + 2], c2);
    }

    if (active) {
        float o0 = mask ? (1.0f / (1.0f + expf(-c0))) : 0.0f;
        float o1 = mask ? (1.0f / (1.0f + expf(-c1))) : 0.0f;
        float o2 = mask ? (1.0f / (1.0f + expf(-c2))) : 0.0f;
        out[3*ray]     = o0;
        out[3*ray + 1] = o1;
        out[3*ray + 2] = o2;
    }
}

extern "C" void kernel_launch(void* const* d_in, const int* in_sizes, int n_in,
                              void* d_out, int out_size)
{
    const float* org = (const float*)d_in[0];
    const float* dir = (const float*)d_in[1];
    const float* W1  = (const float*)d_in[2];
    const float* b1  = (const float*)d_in[3];
    const float* W2  = (const float*)d_in[4];
    const float* b2  = (const float*)d_in[5];
    const float* W3  = (const float*)d_in[6];
    const float* b3  = (const float*)d_in[7];
    const float* Wc1 = (const float*)d_in[8];
    const float* bc1 = (const float*)d_in[9];
    const float* Wc2 = (const float*)d_in[10];
    const float* bc2 = (const float*)d_in[11];
    float* out = (float*)d_out;

    const int N = in_sizes[0] / 3;
    const int smem_bytes = SMEM_FLOATS * sizeof(float);

    cudaFuncSetAttribute(sphere_trace_kernel,
                         cudaFuncAttributeMaxDynamicSharedMemorySize, smem_bytes);

    const int grid = (N + 127) / 128;
    sphere_trace_kernel<<<grid, 128, smem_bytes>>>(
        org, dir, W1, b1, W2, b2, W3, b3, Wc1, bc1, Wc2, bc2, out, N);
}

// round 2
// speedup vs baseline: 1.3249x; 1.3249x over previous
#include <cuda_runtime.h>
#include <math.h>

#define HID 128
#define NEAR_T 0.01f
#define FAR_T 10.0f
#define MAX_IT 32

// ---- packed f32x2 helpers (Blackwell) ----
#define FMA2(acc, a, b) \
    asm("fma.rn.f32x2 %0, %1, %2, %0;" : "+l"(acc) : "l"(a), "l"(b))
#define PACK2(dst, lo, hi) \
    asm("mov.b64 %0, {%1, %2};" : "=l"(dst) : "f"(lo), "f"(hi))
#define UNPACK2(lo, hi, src) \
    asm("mov.b64 {%0, %1}, %2;" : "=f"(lo), "=f"(hi) : "l"(src))

// SMEM layout (float indices):
//  sW1    [3*128] = 384        row-major [3][128]   (used by color-ish init only)
//  sB1    [128]
//  sW2    [128*128] = 16384    row-major [k][o] (as given, NO transpose)
//  sB2    [128]
//  sW3    [128]
//  sWc1   [3*128] = 384
//  sBc1   [128]
//  sWc2   [128*3] = 384
//  sBc2   [4]
//  sW1b   [128*4] = 512        interleaved (W1[0][k],W1[1][k],W1[2][k],b1[k])
//  h1s    [128*128] = 16384    h1s[k*128 + ray]
//  ps     [3*128] = 384        ps[d*128 + ray]
//  part   [128*20] = 2560      partial sdf sums, padded stride 20
//  sfrz   [128] int
//  gfrz   [16] int
#define OFF_W1    0
#define OFF_B1    384
#define OFF_W2    512
#define OFF_B2    16896
#define OFF_W3    17024
#define OFF_WC1   17152
#define OFF_BC1   17536
#define OFF_WC2   17664
#define OFF_BC2   18048
#define OFF_W1B   18052
#define OFF_H1S   18564
#define OFF_PS    34948
#define OFF_PART  35332
#define OFF_INT   37892
#define SMEM_WORDS (37892 + 160)

extern __shared__ float smem[];

__global__ void __launch_bounds__(256, 1)
sphere_trace_kernel(const float* __restrict__ org,
                    const float* __restrict__ dir,
                    const float* __restrict__ W1, const float* __restrict__ b1,
                    const float* __restrict__ W2, const float* __restrict__ b2,
                    const float* __restrict__ W3, const float* __restrict__ b3,
                    const float* __restrict__ Wc1, const float* __restrict__ bc1,
                    const float* __restrict__ Wc2, const float* __restrict__ bc2,
                    float* __restrict__ out, int N)
{
    float* sW1  = smem + OFF_W1;
    float* sB1  = smem + OFF_B1;
    float* sW2  = smem + OFF_W2;
    float* sB2  = smem + OFF_B2;
    float* sW3  = smem + OFF_W3;
    float* sWc1 = smem + OFF_WC1;
    float* sBc1 = smem + OFF_BC1;
    float* sWc2 = smem + OFF_WC2;
    float* sBc2 = smem + OFF_BC2;
    float* sW1b = smem + OFF_W1B;
    float* h1s  = smem + OFF_H1S;
    float* ps   = smem + OFF_PS;
    float* part = smem + OFF_PART;
    int*   sfrz = (int*)(smem + OFF_INT);
    int*   gfrz = sfrz + 128;

    const int t = threadIdx.x;

    // ---- cooperative weight load ----
    for (int i = t; i < 16384; i += 256) sW2[i] = W2[i];
    for (int i = t; i < 384; i += 256) { sW1[i] = W1[i]; sWc1[i] = Wc1[i]; sWc2[i] = Wc2[i]; }
    if (t < 128) { sB1[t] = b1[t]; sB2[t] = b2[t]; sW3[t] = W3[t]; sBc1[t] = bc1[t]; }
    if (t < 4) sBc2[t] = (t < 3) ? bc2[t] : 0.0f;
    if (t < 128) {
        sW1b[t*4 + 0] = W1[t];
        sW1b[t*4 + 1] = W1[HID + t];
        sW1b[t*4 + 2] = W1[2*HID + t];
        sW1b[t*4 + 3] = b1[t];
    }
    const float bias3 = b3[0];

    // ---- ray init ----
    const int rbase = blockIdx.x * 128;
    const int r = t & 127;
    int ray = rbase + r;
    if (ray >= N) ray = N - 1;

    float dx = 0.f, dy = 0.f, dz = 0.f, dist = 0.f;
    bool hit = false;
    if (t < 128) {
        ps[r]       = org[3*ray];
        ps[128 + r] = org[3*ray + 1];
        ps[256 + r] = org[3*ray + 2];
        dx = dir[3*ray]; dy = dir[3*ray + 1]; dz = dir[3*ray + 2];
        sfrz[r] = 0;
    }
    if (t < 16) gfrz[t] = 0;
    __syncthreads();

    // ---- GEMM thread mapping: 16 (ray groups) x 16 (out groups) of 8x8 tiles ----
    const int tr = t >> 4;       // 0..15 -> rays [tr*8, tr*8+8)
    const int tc = t & 15;       // 0..15 -> outs [tc*8, tc*8+8)
    const int r0 = tr * 8;
    const int o0 = tc * 8;
    const int kbase = (t >> 7) * 64;   // phase-A half

    for (int it = 0; it < MAX_IT; ++it) {
        // ===== phase A: layer 1, h1s[k][r] = relu(p . W1[:,k] + b1[k]) =====
        if (!sfrz[r]) {
            const float px = ps[r], py = ps[128 + r], pz = ps[256 + r];
            #pragma unroll 8
            for (int k = kbase; k < kbase + 64; ++k) {
                float4 q = *reinterpret_cast<const float4*>(&sW1b[k*4]);
                float h = fmaf(px, q.x, fmaf(py, q.y, fmaf(pz, q.z, q.w)));
                h1s[k*128 + r] = fmaxf(h, 0.0f);
            }
        }
        __syncthreads();

        // ===== phase B: layer 2 GEMM + layer 3 partials =====
        float ssum[8];
        #pragma unroll
        for (int i = 0; i < 8; ++i) ssum[i] = 0.0f;

        if (!gfrz[tr]) {
            unsigned long long acc[8][4];
            {
                float4 bb0 = *reinterpret_cast<const float4*>(&sB2[o0]);
                float4 bb1 = *reinterpret_cast<const float4*>(&sB2[o0 + 4]);
                unsigned long long bp[4];
                PACK2(bp[0], bb0.x, bb0.y); PACK2(bp[1], bb0.z, bb0.w);
                PACK2(bp[2], bb1.x, bb1.y); PACK2(bp[3], bb1.z, bb1.w);
                #pragma unroll
                for (int i = 0; i < 8; ++i) {
                    acc[i][0] = bp[0]; acc[i][1] = bp[1];
                    acc[i][2] = bp[2]; acc[i][3] = bp[3];
                }
            }

            #pragma unroll 4
            for (int k = 0; k < HID; ++k) {
                float4 a0 = *reinterpret_cast<const float4*>(&h1s[k*128 + r0]);
                float4 a1 = *reinterpret_cast<const float4*>(&h1s[k*128 + r0 + 4]);
                float4 w0 = *reinterpret_cast<const float4*>(&sW2[k*128 + o0]);
                float4 w1 = *reinterpret_cast<const float4*>(&sW2[k*128 + o0 + 4]);
                unsigned long long wp[4];
                PACK2(wp[0], w0.x, w0.y); PACK2(wp[1], w0.z, w0.w);
                PACK2(wp[2], w1.x, w1.y); PACK2(wp[3], w1.z, w1.w);
                float av[8] = {a0.x, a0.y, a0.z, a0.w, a1.x, a1.y, a1.z, a1.w};
                #pragma unroll
                for (int i = 0; i < 8; ++i) {
                    unsigned long long aa;
                    PACK2(aa, av[i], av[i]);
                    FMA2(acc[i][0], aa, wp[0]);
                    FMA2(acc[i][1], aa, wp[1]);
                    FMA2(acc[i][2], aa, wp[2]);
                    FMA2(acc[i][3], aa, wp[3]);
                }
            }

            // layer-3 partial: ssum[i] = sum_{o in tile} relu(h2) * W3[o]
            float4 w30 = *reinterpret_cast<const float4*>(&sW3[o0]);
            float4 w31 = *reinterpret_cast<const float4*>(&sW3[o0 + 4]);
            #pragma unroll
            for (int i = 0; i < 8; ++i) {
                float v0, v1, v2, v3, v4, v5, v6, v7;
                UNPACK2(v0, v1, acc[i][0]);
                UNPACK2(v2, v3, acc[i][1]);
                UNPACK2(v4, v5, acc[i][2]);
                UNPACK2(v6, v7, acc[i][3]);
                float s = fmaxf(v0, 0.f) * w30.x;
                s = fmaf(fmaxf(v1, 0.f), w30.y, s);
                s = fmaf(fmaxf(v2, 0.f), w30.z, s);
                s = fmaf(fmaxf(v3, 0.f), w30.w, s);
                s = fmaf(fmaxf(v4, 0.f), w31.x, s);
                s = fmaf(fmaxf(v5, 0.f), w31.y, s);
                s = fmaf(fmaxf(v6, 0.f), w31.z, s);
                s = fmaf(fmaxf(v7, 0.f), w31.w, s);
                ssum[i] = s;
            }
        }
        #pragma unroll
        for (int i = 0; i < 8; ++i) part[(r0 + i) * 20 + tc] = ssum[i];
        __syncthreads();

        // ===== phase C: per-ray reduce + march update (owner threads) =====
        int myfrozen = 1;
        if (t < 128) {
            myfrozen = sfrz[r];
            if (!myfrozen) {
                const float* pp = &part[r * 20];
                float4 p0 = *reinterpret_cast<const float4*>(pp);
                float4 p1 = *reinterpret_cast<const float4*>(pp + 4);
                float4 p2 = *reinterpret_cast<const float4*>(pp + 8);
                float4 p3 = *reinterpret_cast<const float4*>(pp + 12);
                float sdf = bias3
                          + ((p0.x + p0.y) + (p0.z + p0.w))
                          + ((p1.x + p1.y) + (p1.z + p1.w))
                          + ((p2.x + p2.y) + (p2.z + p2.w))
                          + ((p3.x + p3.y) + (p3.z + p3.w));
                const bool valid = (sdf <= NEAR_T) && (dist < FAR_T);
                hit = hit || valid;
                if (valid) {
                    sfrz[r] = 1;
                    myfrozen = 1;
                } else {
                    dist += sdf;
                    ps[r]       = fmaf(dx, sdf, ps[r]);
                    ps[128 + r] = fmaf(dy, sdf, ps[128 + r]);
                    ps[256 + r] = fmaf(dz, sdf, ps[256 + r]);
                }
            }
            // per-8-ray group frozen flags via ballot (warps 0..3 fully inside t<128)
            unsigned bal = __ballot_sync(0xffffffffu, myfrozen);
            int g = (t & 31) >> 3;
            unsigned msk = 0xFFu << (g * 8);
            if ((t & 7) == 0) gfrz[t >> 3] = ((bal & msk) == msk) ? 1 : 0;
        }
        int alldone = __syncthreads_and(myfrozen);
        if (alldone) break;
    }

    // ===== color MLP (owner threads) =====
    if (t < 128 && (rbase + r) < N) {
        const float px = ps[r], py = ps[128 + r], pz = ps[256 + r];
        const bool mask = hit || (dist < FAR_T);
        float c0 = sBc2[0], c1 = sBc2[1], c2 = sBc2[2];
        for (int j = 0; j < HID; ++j) {
            float h = fmaf(px, sWc1[j],
                      fmaf(py, sWc1[HID + j],
                      fmaf(pz, sWc1[2*HID + j], sBc1[j])));
            h = fmaxf(h, 0.0f);
            c0 = fmaf(h, sWc2[3*j],     c0);
            c1 = fmaf(h, sWc2[3*j + 1], c1);
            c2 = fmaf(h, sWc2[3*j + 2], c2);
        }
        const int oray = rbase + r;
        out[3*oray]     = mask ? (1.0f / (1.0f + expf(-c0))) : 0.0f;
        out[3*oray + 1] = mask ? (1.0f / (1.0f + expf(-c1))) : 0.0f;
        out[3*oray + 2] = mask ? (1.0f / (1.0f + expf(-c2))) : 0.0f;
    }
}

extern "C" void kernel_launch(void* const* d_in, const int* in_sizes, int n_in,
                              void* d_out, int out_size)
{
    const float* org = (const float*)d_in[0];
    const float* dir = (const float*)d_in[1];
    const float* W1  = (const float*)d_in[2];
    const float* b1  = (const float*)d_in[3];
    const float* W2  = (const float*)d_in[4];
    const float* b2  = (const float*)d_in[5];
    const float* W3  = (const float*)d_in[6];
    const float* b3  = (const float*)d_in[7];
    const float* Wc1 = (const float*)d_in[8];
    const float* bc1 = (const float*)d_in[9];
    const float* Wc2 = (const float*)d_in[10];
    const float* bc2 = (const float*)d_in[11];
    float* out = (float*)d_out;

    const int N = in_sizes[0] / 3;
    const int smem_bytes = SMEM_WORDS * sizeof(float);

    cudaFuncSetAttribute(sphere_trace_kernel,
                         cudaFuncAttributeMaxDynamicSharedMemorySize, smem_bytes);

    const int grid = (N + 127) / 128;
    sphere_trace_kernel<<<grid, 128 /*unused*/ + 128, smem_bytes>>>(
        org, dir, W1, b1, W2, b2, W3, b3, Wc1, bc1, Wc2, bc2, out, N);
}

// round 3
// speedup vs baseline: 1.5084x; 1.1384x over previous
#include <cuda_runtime.h>
#include <math.h>

#define HID 128
#define NEAR_T 0.01f
#define FAR_T 10.0f
#define MAX_IT 32
#define RAYS_PER_TILE 256
#define NTHREADS 512

// ---- packed f32x2 helpers (Blackwell) ----
#define FMA2(acc, a, b) \
    asm("fma.rn.f32x2 %0, %1, %2, %0;" : "+l"(acc) : "l"(a), "l"(b))
#define PACK2(dst, lo, hi) \
    asm("mov.b64 %0, {%1, %2};" : "=l"(dst) : "f"(lo), "f"(hi))
#define UNPACK2(lo, hi, src) \
    asm("mov.b64 {%0, %1}, %2;" : "=f"(lo), "=f"(hi) : "l"(src))

// SMEM layout (float word offsets)
#define OFF_W2    0                    // 16384 : W2 row-major [k][o]
#define OFF_H1    16384                // 32768 : h1s[k*256 + ray]
#define OFF_W1B   49152                // 512   : (W1x,W1y,W1z,b1) interleaved
#define OFF_WC1B  49664                // 512   : (Wc1x,Wc1y,Wc1z,bc1)
#define OFF_WC2B  50176                // 512   : (Wc2[j][0..2], 0)
#define OFF_B2    50688                // 128
#define OFF_W3    50816                // 128
#define OFF_BC2   50944                // 16 (pad)
#define OFF_PS    50960                // 768 : ps[d*256 + ray]
#define OFF_PART  51728                // 256*17 = 4352
#define OFF_INT   56080                // sfrz 256 + gfrz 32 + stile 4
#define SMEM_WORDS (56080 + 296)

__device__ int g_tile_ctr;

__global__ void reset_ctr_kernel() { g_tile_ctr = 0; }

extern __shared__ float smem[];

__global__ void __launch_bounds__(NTHREADS, 1)
sphere_trace_kernel(const float* __restrict__ org,
                    const float* __restrict__ dir,
                    const float* __restrict__ W1, const float* __restrict__ b1,
                    const float* __restrict__ W2, const float* __restrict__ b2,
                    const float* __restrict__ W3, const float* __restrict__ b3,
                    const float* __restrict__ Wc1, const float* __restrict__ bc1,
                    const float* __restrict__ Wc2, const float* __restrict__ bc2,
                    float* __restrict__ out, int N, int ntiles)
{
    float* sW2   = smem + OFF_W2;
    float* h1s   = smem + OFF_H1;
    float* sW1b  = smem + OFF_W1B;
    float* sWc1b = smem + OFF_WC1B;
    float* sWc2b = smem + OFF_WC2B;
    float* sB2   = smem + OFF_B2;
    float* sW3   = smem + OFF_W3;
    float* sBc2  = smem + OFF_BC2;
    float* ps    = smem + OFF_PS;
    float* part  = smem + OFF_PART;
    int*   sfrz  = (int*)(smem + OFF_INT);
    int*   gfrz  = sfrz + 256;
    int*   stile = gfrz + 32;

    const int t = threadIdx.x;

    // ---- one-time weight staging ----
    for (int i = t; i < 16384; i += NTHREADS) sW2[i] = W2[i];
    if (t < 128) {
        sB2[t] = b2[t];
        sW3[t] = W3[t];
        sW1b[t*4 + 0] = W1[t];
        sW1b[t*4 + 1] = W1[HID + t];
        sW1b[t*4 + 2] = W1[2*HID + t];
        sW1b[t*4 + 3] = b1[t];
        sWc1b[t*4 + 0] = Wc1[t];
        sWc1b[t*4 + 1] = Wc1[HID + t];
        sWc1b[t*4 + 2] = Wc1[2*HID + t];
        sWc1b[t*4 + 3] = bc1[t];
        sWc2b[t*4 + 0] = Wc2[3*t];
        sWc2b[t*4 + 1] = Wc2[3*t + 1];
        sWc2b[t*4 + 2] = Wc2[3*t + 2];
        sWc2b[t*4 + 3] = 0.0f;
    }
    if (t < 4) sBc2[t] = (t < 3) ? bc2[t] : 0.0f;
    const float bias3 = b3[0];

    // thread mappings
    const int r      = t & 255;          // owner ray (t < 256)
    const int kbase  = (t >> 8) * 64;    // phase-A k half
    const int tr     = t >> 4;           // GEMM: ray group 0..31
    const int tc     = t & 15;           // GEMM: out group 0..15
    const int r0     = tr * 8;
    const int o0     = tc * 8;

    // ---- persistent tile loop ----
    for (;;) {
        if (t == 0) stile[0] = atomicAdd(&g_tile_ctr, 1);
        __syncthreads();                 // also orders prev-tile reads vs init writes
        const int tile = stile[0];
        if (tile >= ntiles) break;

        const int rbase = tile * RAYS_PER_TILE;

        float dx = 0.f, dy = 0.f, dz = 0.f, dist = 0.f;
        bool hit = false;
        if (t < 256) {
            int ray = rbase + r;
            if (ray >= N) ray = N - 1;
            ps[r]       = org[3*ray];
            ps[256 + r] = org[3*ray + 1];
            ps[512 + r] = org[3*ray + 2];
            dx = dir[3*ray]; dy = dir[3*ray + 1]; dz = dir[3*ray + 2];
            sfrz[r] = 0;
        }
        if (t < 32) gfrz[t] = 0;
        __syncthreads();

        for (int it = 0; it < MAX_IT; ++it) {
            // ===== phase A: layer 1 =====
            if (!sfrz[r]) {
                const float px = ps[r], py = ps[256 + r], pz = ps[512 + r];
                #pragma unroll 8
                for (int k = kbase; k < kbase + 64; ++k) {
                    float4 q = *reinterpret_cast<const float4*>(&sW1b[k*4]);
                    float h = fmaf(px, q.x, fmaf(py, q.y, fmaf(pz, q.z, q.w)));
                    h1s[k*256 + r] = fmaxf(h, 0.0f);
                }
            }
            __syncthreads();

            // ===== phase B: layer 2 GEMM + layer 3 partials =====
            float ssum[8];
            #pragma unroll
            for (int i = 0; i < 8; ++i) ssum[i] = 0.0f;

            if (!gfrz[tr]) {
                unsigned long long acc[8][4];
                {
                    float4 bb0 = *reinterpret_cast<const float4*>(&sB2[o0]);
                    float4 bb1 = *reinterpret_cast<const float4*>(&sB2[o0 + 4]);
                    unsigned long long bp[4];
                    PACK2(bp[0], bb0.x, bb0.y); PACK2(bp[1], bb0.z, bb0.w);
                    PACK2(bp[2], bb1.x, bb1.y); PACK2(bp[3], bb1.z, bb1.w);
                    #pragma unroll
                    for (int i = 0; i < 8; ++i) {
                        acc[i][0] = bp[0]; acc[i][1] = bp[1];
                        acc[i][2] = bp[2]; acc[i][3] = bp[3];
                    }
                }

                const float* ap = &h1s[r0];
                const float* wp2 = &sW2[o0];
                #pragma unroll 4
                for (int k = 0; k < HID; ++k) {
                    float4 a0 = *reinterpret_cast<const float4*>(ap);
                    float4 a1 = *reinterpret_cast<const float4*>(ap + 4);
                    float4 w0 = *reinterpret_cast<const float4*>(wp2);
                    float4 w1 = *reinterpret_cast<const float4*>(wp2 + 4);
                    ap += 256; wp2 += 128;
                    unsigned long long wp[4];
                    PACK2(wp[0], w0.x, w0.y); PACK2(wp[1], w0.z, w0.w);
                    PACK2(wp[2], w1.x, w1.y); PACK2(wp[3], w1.z, w1.w);
                    float av[8] = {a0.x, a0.y, a0.z, a0.w, a1.x, a1.y, a1.z, a1.w};
                    #pragma unroll
                    for (int i = 0; i < 8; ++i) {
                        unsigned long long aa;
                        PACK2(aa, av[i], av[i]);
                        FMA2(acc[i][0], aa, wp[0]);
                        FMA2(acc[i][1], aa, wp[1]);
                        FMA2(acc[i][2], aa, wp[2]);
                        FMA2(acc[i][3], aa, wp[3]);
                    }
                }

                float4 w30 = *reinterpret_cast<const float4*>(&sW3[o0]);
                float4 w31 = *reinterpret_cast<const float4*>(&sW3[o0 + 4]);
                #pragma unroll
                for (int i = 0; i < 8; ++i) {
                    float v0, v1, v2, v3, v4, v5, v6, v7;
                    UNPACK2(v0, v1, acc[i][0]);
                    UNPACK2(v2, v3, acc[i][1]);
                    UNPACK2(v4, v5, acc[i][2]);
                    UNPACK2(v6, v7, acc[i][3]);
                    float s = fmaxf(v0, 0.f) * w30.x;
                    s = fmaf(fmaxf(v1, 0.f), w30.y, s);
                    s = fmaf(fmaxf(v2, 0.f), w30.z, s);
                    s = fmaf(fmaxf(v3, 0.f), w30.w, s);
                    s = fmaf(fmaxf(v4, 0.f), w31.x, s);
                    s = fmaf(fmaxf(v5, 0.f), w31.y, s);
                    s = fmaf(fmaxf(v6, 0.f), w31.z, s);
                    s = fmaf(fmaxf(v7, 0.f), w31.w, s);
                    ssum[i] = s;
                }
            }
            #pragma unroll
            for (int i = 0; i < 8; ++i) part[(r0 + i) * 17 + tc] = ssum[i];
            __syncthreads();

            // ===== phase C: per-ray reduce + march update =====
            int myfrozen = 1;
            if (t < 256) {
                myfrozen = sfrz[r];
                if (!myfrozen) {
                    const float* pp = &part[r * 17];
                    float s0 = 0.f, s1 = 0.f, s2 = 0.f, s3 = 0.f;
                    #pragma unroll
                    for (int j = 0; j < 16; j += 4) {
                        s0 += pp[j]; s1 += pp[j+1]; s2 += pp[j+2]; s3 += pp[j+3];
                    }
                    float sdf = bias3 + ((s0 + s1) + (s2 + s3));
                    const bool valid = (sdf <= NEAR_T) && (dist < FAR_T);
                    hit = hit || valid;
                    if (valid) {
                        sfrz[r] = 1;
                        myfrozen = 1;
                    } else {
                        dist += sdf;
                        ps[r]       = fmaf(dx, sdf, ps[r]);
                        ps[256 + r] = fmaf(dy, sdf, ps[256 + r]);
                        ps[512 + r] = fmaf(dz, sdf, ps[512 + r]);
                    }
                }
                unsigned bal = __ballot_sync(0xffffffffu, myfrozen);
                int g = (t & 31) >> 3;
                unsigned msk = 0xFFu << (g * 8);
                if ((t & 7) == 0) gfrz[t >> 3] = ((bal & msk) == msk) ? 1 : 0;
            }
            int alldone = __syncthreads_and(myfrozen);
            if (alldone) break;
        }

        // ===== color MLP (owner threads) =====
        if (t < 256 && (rbase + r) < N) {
            const float px = ps[r], py = ps[256 + r], pz = ps[512 + r];
            const bool mask = hit || (dist < FAR_T);
            float c0 = sBc2[0], c1 = sBc2[1], c2 = sBc2[2];
            #pragma unroll 4
            for (int j = 0; j < HID; ++j) {
                float4 q = *reinterpret_cast<const float4*>(&sWc1b[j*4]);
                float4 w = *reinterpret_cast<const float4*>(&sWc2b[j*4]);
                float h = fmaf(px, q.x, fmaf(py, q.y, fmaf(pz, q.z, q.w)));
                h = fmaxf(h, 0.0f);
                c0 = fmaf(h, w.x, c0);
                c1 = fmaf(h, w.y, c1);
                c2 = fmaf(h, w.z, c2);
            }
            const int oray = rbase + r;
            out[3*oray]     = mask ? (1.0f / (1.0f + expf(-c0))) : 0.0f;
            out[3*oray + 1] = mask ? (1.0f / (1.0f + expf(-c1))) : 0.0f;
            out[3*oray + 2] = mask ? (1.0f / (1.0f + expf(-c2))) : 0.0f;
        }
        // next tile (sync at top of loop protects ps reuse)
    }
}

extern "C" void kernel_launch(void* const* d_in, const int* in_sizes, int n_in,
                              void* d_out, int out_size)
{
    const float* org = (const float*)d_in[0];
    const float* dir = (const float*)d_in[1];
    const float* W1  = (const float*)d_in[2];
    const float* b1  = (const float*)d_in[3];
    const float* W2  = (const float*)d_in[4];
    const float* b2  = (const float*)d_in[5];
    const float* W3  = (const float*)d_in[6];
    const float* b3  = (const float*)d_in[7];
    const float* Wc1 = (const float*)d_in[8];
    const float* bc1 = (const float*)d_in[9];
    const float* Wc2 = (const float*)d_in[10];
    const float* bc2 = (const float*)d_in[11];
    float* out = (float*)d_out;

    const int N = in_sizes[0] / 3;
    const int ntiles = (N + RAYS_PER_TILE - 1) / RAYS_PER_TILE;
    const int smem_bytes = SMEM_WORDS * sizeof(float);

    cudaFuncSetAttribute(sphere_trace_kernel,
                         cudaFuncAttributeMaxDynamicSharedMemorySize, smem_bytes);

    reset_ctr_kernel<<<1, 1>>>();

    int nblocks = 152;                 // persistent: one per SM (GB300)
    if (nblocks > ntiles) nblocks = ntiles;
    sphere_trace_kernel<<<nblocks, NTHREADS, smem_bytes>>>(
        org, dir, W1, b1, W2, b2, W3, b3, Wc1, bc1, Wc2, bc2, out, N, ntiles);
}